// round 9
// baseline (speedup 1.0000x reference)
#include <cuda_runtime.h>
#include <cstdint>

#define BB 2
#define LL 2048
#define HH 16
#define EE 64
#define NKT 32

// Plain roped Q/K, [bh][l][d] layout (pack-kernel friendly)
__device__ float g_Qr[BB * HH * LL * EE];
__device__ float g_Kr[BB * HH * LL * EE];
// Frag-major packed operands (tf32 bits). One warp LDG.128 = 32 consecutive uint4.
//  g_Qf/g_Kf: [bh][rowgrp(256)][kbp(4)][lane(32)]
//  g_Vf:      [bh][kt(32)][nbp(4)][db(8)][lane(32)]
__device__ uint4 g_Qf[BB * HH * 256 * 4 * 32];
__device__ uint4 g_Kf[BB * HH * 256 * 4 * 32];
__device__ uint4 g_Vf[BB * HH * NKT * 4 * 8 * 32];

#define LOG2E 1.4426950408889634f
#define SCL2  0.18033688011112042592f   // 0.125 * log2(e)

__device__ __forceinline__ uint32_t f2tf(float x) {
    uint32_t u;
    asm("cvt.rna.tf32.f32 %0, %1;" : "=r"(u) : "f"(x));
    return u;
}
__device__ __forceinline__ float ex2f(float x) {
    float o;
    asm("ex2.approx.f32 %0, %1;" : "=f"(o) : "f"(x));
    return o;
}
__device__ __forceinline__ void mma8(float c[4], const uint32_t a[4],
                                     uint32_t b0, uint32_t b1) {
    asm volatile(
        "mma.sync.aligned.m16n8k8.row.col.f32.tf32.tf32.f32 "
        "{%0,%1,%2,%3}, {%4,%5,%6,%7}, {%8,%9}, {%0,%1,%2,%3};"
        : "+f"(c[0]), "+f"(c[1]), "+f"(c[2]), "+f"(c[3])
        : "r"(a[0]), "r"(a[1]), "r"(a[2]), "r"(a[3]), "r"(b0), "r"(b1));
}

// ---------------------------------------------------------------------------
// Prepass 1: RoPE Q,K -> g_Qr/g_Kr in [bh][l][d] layout.
// ---------------------------------------------------------------------------
__global__ void rope_kernel(const float* __restrict__ q,
                            const float* __restrict__ k) {
    int idx = blockIdx.x * blockDim.x + threadIdx.x;
    const int N4 = BB * LL * HH * 16;
    if (idx >= N4) return;
    int e4  = idx & 15;
    int row = idx >> 4;
    int h = row & 15;
    int bl = row >> 4;
    int l = bl & (LL - 1);
    int b = bl >> 11;
    float4 vq = ((const float4*)q)[idx];
    float4 vk = ((const float4*)k)[idx];
    if (e4 < 8) {
        float i0 = (float)(e4 * 2);
        const float NEG_L2 = -0.83048202372184058696f;  // -log2(10000)/16
        float s0, c0, s1, c1;
        sincosf((float)l * exp2f(i0 * NEG_L2), &s0, &c0);
        sincosf((float)l * exp2f((i0 + 1.0f) * NEG_L2), &s1, &c1);
        float4 o;
        o.x = c0 * vq.x - s0 * vq.y;  o.y = c0 * vq.y + s0 * vq.x;
        o.z = c1 * vq.z - s1 * vq.w;  o.w = c1 * vq.w + s1 * vq.z;
        vq = o;
        o.x = c0 * vk.x - s0 * vk.y;  o.y = c0 * vk.y + s0 * vk.x;
        o.z = c1 * vk.z - s1 * vk.w;  o.w = c1 * vk.w + s1 * vk.z;
        vk = o;
    }
    size_t base = (((size_t)(b * HH + h) * LL + l) * EE + e4 * 4) / 4;
    ((float4*)g_Qr)[base] = vq;
    ((float4*)g_Kr)[base] = vk;
}

// ---------------------------------------------------------------------------
// Prepass 2: frag-major pack of Q, K, V per (b, h, kt) 64-row tile.
// ---------------------------------------------------------------------------
__global__ void pack_kernel(const float* __restrict__ v) {
    __shared__ float vs[64 * 65];
    const int kt = blockIdx.x, h = blockIdx.y, b = blockIdx.z;
    const int bh = b * HH + h;
    const int tid = threadIdx.x;

    const float* Vg = v + ((size_t)(b * LL + kt * 64) * HH + h) * EE;
    #pragma unroll
    for (int it = 0; it < 4; it++) {
        int i = it * 256 + tid;
        int j = i >> 4, e = (i & 15) * 4;
        float4 w = *(const float4*)(Vg + (size_t)j * (HH * EE) + e);
        vs[j * 65 + e + 0] = w.x; vs[j * 65 + e + 1] = w.y;
        vs[j * 65 + e + 2] = w.z; vs[j * 65 + e + 3] = w.w;
    }
    __syncthreads();

    const float* Qr = g_Qr + ((size_t)bh * LL + kt * 64) * EE;
    const float* Kr = g_Kr + ((size_t)bh * LL + kt * 64) * EE;
    uint4* Qf = g_Qf + ((size_t)bh * 256 + kt * 8) * 128;
    uint4* Kf = g_Kf + ((size_t)bh * 256 + kt * 8) * 128;
    #pragma unroll
    for (int it = 0; it < 4; it++) {
        int i = it * 256 + tid;
        int lane = i & 31, x = i >> 5;       // x = nb*4 + kbp
        int nb = x >> 2, kbp = x & 3;
        int g = lane >> 2, t = lane & 3;
        const float* qs = Qr + (size_t)(nb * 8 + g) * EE + kbp * 16 + t;
        uint4 o;
        o.x = f2tf(qs[0]); o.y = f2tf(qs[4]); o.z = f2tf(qs[8]); o.w = f2tf(qs[12]);
        Qf[x * 32 + lane] = o;
        const float* ks = Kr + (size_t)(nb * 8 + g) * EE + kbp * 16 + t;
        o.x = f2tf(ks[0]); o.y = f2tf(ks[4]); o.z = f2tf(ks[8]); o.w = f2tf(ks[12]);
        Kf[x * 32 + lane] = o;
    }

    uint4* Vf = g_Vf + ((size_t)bh * NKT + kt) * 1024;
    #pragma unroll
    for (int it = 0; it < 4; it++) {
        int i = it * 256 + tid;
        int lane = i & 31, x = i >> 5;       // x = nbp*8 + db
        int nbp = x >> 3, db = x & 7;
        int g = lane >> 2, t = lane & 3;
        const float* vb = vs + (16 * nbp + t) * 65 + db * 8 + g;
        uint4 o;
        o.x = f2tf(vb[0]);
        o.y = f2tf(vb[4 * 65]);
        o.z = f2tf(vb[8 * 65]);
        o.w = f2tf(vb[12 * 65]);
        Vf[x * 32 + lane] = o;
    }
}

// ---------------------------------------------------------------------------
// One (kt, tile-depth) body: dep+1 key blocks, QK -> softmax -> PV.
// Q frags loaded lazily per kbp from frag-major pack (L1 hits).
// ---------------------------------------------------------------------------
__device__ __forceinline__ void tile_body(
    int kt, int dep, int n0, const uint4* __restrict__ Qf,
    const uint4* __restrict__ Kf0, const uint4* __restrict__ Vf0,
    float biasA, float biasB, int src0, int src1, bool odd, int t,
    float (&oacc)[8][4], float& lsA, float& lsB)
{
    const uint4* Kt = Kf0 + (size_t)kt * 1024;
    const uint4* Vt = Vf0 + (size_t)kt * 1024;

    #pragma unroll
    for (int nbp = 0; nbp < 4; nbp++) {
        const int nb0 = 2 * nbp, nb1 = nb0 + 1;
        if (nb0 > dep) continue;                // warp-uniform prune
        const bool a1 = (nb1 <= dep);

        // ---- K frags (coalesced LDG.128) ----
        uint4 kq0[4], kq1[4];
        #pragma unroll
        for (int kbp = 0; kbp < 4; kbp++)
            kq0[kbp] = Kt[nb0 * 128 + kbp * 32];
        if (a1) {
            #pragma unroll
            for (int kbp = 0; kbp < 4; kbp++)
                kq1[kbp] = Kt[nb1 * 128 + kbp * 32];
        }

        // ---- S = Q K^T (lazy Q frag loads) ----
        float c0[4] = {0, 0, 0, 0}, c1[4] = {0, 0, 0, 0};
        #pragma unroll
        for (int kbp = 0; kbp < 4; kbp++) {
            uint4 qx = Qf[kbp * 32];            // var-A rowgrp
            uint4 qy = Qf[8 * 128 + kbp * 32];  // var-B rowgrp
            uint32_t aE[4] = {qx.x, qy.x, qx.y, qy.y};
            uint32_t aO[4] = {qx.z, qy.z, qx.w, qy.w};
            mma8(c0, aE, kq0[kbp].x, kq0[kbp].y);
            if (a1) mma8(c1, aE, kq1[kbp].x, kq1[kbp].y);
            mma8(c0, aO, kq0[kbp].z, kq0[kbp].w);
            if (a1) mma8(c1, aO, kq1[kbp].z, kq1[kbp].w);
        }

        // ---- softmax + P frag relayout (quad shuffles) ----
        uint32_t pa0[4], pa1[4];
        #pragma unroll
        for (int nbi = 0; nbi < 2; nbi++) {
            if (nbi && !a1) continue;
            float* c = nbi ? c1 : c0;
            const int ci = (nb0 + nbi) * 8 + 2 * t;
            float p0 = (ci     <= n0) ? ex2f(fmaf(c[0], SCL2, biasA)) : 0.0f;
            float p1 = (ci + 1 <= n0) ? ex2f(fmaf(c[1], SCL2, biasA)) : 0.0f;
            float p2 = (ci     <= n0) ? ex2f(fmaf(c[2], SCL2, biasB)) : 0.0f;
            float p3 = (ci + 1 <= n0) ? ex2f(fmaf(c[3], SCL2, biasB)) : 0.0f;
            lsA += p0 + p1;
            lsB += p2 + p3;
            uint32_t* pa = nbi ? pa1 : pa0;
            uint32_t u0 = f2tf(p0), u1 = f2tf(p1), u2 = f2tf(p2), u3 = f2tf(p3);
            uint32_t x0 = __shfl_sync(0xffffffffu, u0, src0);
            uint32_t x1 = __shfl_sync(0xffffffffu, u1, src0);
            pa[0] = odd ? x1 : x0;
            uint32_t y0 = __shfl_sync(0xffffffffu, u2, src0);
            uint32_t y1 = __shfl_sync(0xffffffffu, u3, src0);
            pa[1] = odd ? y1 : y0;
            uint32_t z0 = __shfl_sync(0xffffffffu, u0, src1);
            uint32_t z1 = __shfl_sync(0xffffffffu, u1, src1);
            pa[2] = odd ? z1 : z0;
            uint32_t w0 = __shfl_sync(0xffffffffu, u2, src1);
            uint32_t w1 = __shfl_sync(0xffffffffu, u3, src1);
            pa[3] = odd ? w1 : w0;
        }

        // ---- O += P V ----
        #pragma unroll
        for (int db = 0; db < 8; db++) {
            uint4 vq = Vt[nbp * 256 + db * 32];
            mma8(oacc[db], pa0, vq.x, vq.y);
            if (a1) mma8(oacc[db], pa1, vq.z, vq.w);
        }
    }
}

// ---------------------------------------------------------------------------
// Main attention with kt-parity work balancing.
// 256 threads = 8 warps; CTA = 128 query rows = 8 depth tiles.
// Warp w: even kt -> tile depth w; odd kt -> tile depth 7-w.
// Every warp does exactly 9 blocks per kt-pair (perfect balance, exact
// triangle). Tile d's partials (warp d evens + warp 7-d odds) combine at
// the end through smem; no-max softmax makes O and lsum purely additive.
// ---------------------------------------------------------------------------
__global__ __launch_bounds__(256, 2)
void attn7(const float* __restrict__ bw, float* __restrict__ out) {
    __shared__ float smx[8][34][32];   // [tile][32 O regs + 2 lsums][lane]

    const int tid  = threadIdx.x;
    const int lane = tid & 31;
    const int w    = tid >> 5;
    const int g    = lane >> 2;
    const int t    = lane & 3;
    const int qtb  = blockIdx.x;
    const int h    = blockIdx.y;
    const int b    = blockIdx.z;
    const int bh   = b * HH + h;
    const int l0   = qtb * 128;

    const int depA = w;
    const int depB = 7 - w;
    const int n0A  = 8 * depA + g;
    const int n0B  = 8 * depB + g;

    const float b2s = bw[HH + h] * LOG2E;
    const float b2d = bw[h] * LOG2E;

    const uint4* QfA = g_Qf + ((size_t)bh * 256 + qtb * 16 + depA) * 128 + lane;
    const uint4* QfB = g_Qf + ((size_t)bh * 256 + qtb * 16 + depB) * 128 + lane;
    const uint4* Kf0 = g_Kf + (size_t)bh * 256 * 128 + lane;
    const uint4* Vf0 = g_Vf + (size_t)bh * NKT * 1024 + lane;

    float oA[8][4], oB[8][4];
    #pragma unroll
    for (int db = 0; db < 8; db++)
        #pragma unroll
        for (int i = 0; i < 4; i++) { oA[db][i] = 0.0f; oB[db][i] = 0.0f; }
    float lsAA = 0.0f, lsAB = 0.0f;    // tile A: var-A rows, var-B rows
    float lsBA = 0.0f, lsBB = 0.0f;    // tile B

    const int  src0 = (lane & ~3) + (t >> 1);
    const int  src1 = src0 + 2;
    const bool odd  = (t & 1);

    for (int ktp = 0; ktp < 16; ktp++) {
        {   // even kt -> tile A (depth w)
            const int kt = 2 * ktp;
            const float biasA = (kt == 2 * qtb)     ? b2s : b2d;
            const float biasB = (kt == 2 * qtb + 1) ? b2s : b2d;
            tile_body(kt, depA, n0A, QfA, Kf0, Vf0, biasA, biasB,
                      src0, src1, odd, t, oA, lsAA, lsAB);
        }
        {   // odd kt -> tile B (depth 7-w)
            const int kt = 2 * ktp + 1;
            const float biasA = (kt == 2 * qtb)     ? b2s : b2d;
            const float biasB = (kt == 2 * qtb + 1) ? b2s : b2d;
            tile_body(kt, depB, n0B, QfB, Kf0, Vf0, biasA, biasB,
                      src0, src1, odd, t, oB, lsBA, lsBB);
        }
    }

    // ---- exchange tile-B partials, combine into tile-A owners ----
    #pragma unroll
    for (int db = 0; db < 8; db++)
        #pragma unroll
        for (int i = 0; i < 4; i++)
            smx[depB][db * 4 + i][lane] = oB[db][i];
    smx[depB][32][lane] = lsBA;
    smx[depB][33][lane] = lsBB;
    __syncthreads();

    #pragma unroll
    for (int db = 0; db < 8; db++)
        #pragma unroll
        for (int i = 0; i < 4; i++)
            oA[db][i] += smx[depA][db * 4 + i][lane];
    lsAA += smx[depA][32][lane];
    lsAB += smx[depA][33][lane];

    // ---- reduce row sums across quad, normalize, store tile depA ----
    lsAA += __shfl_xor_sync(0xffffffffu, lsAA, 1);
    lsAA += __shfl_xor_sync(0xffffffffu, lsAA, 2);
    lsAB += __shfl_xor_sync(0xffffffffu, lsAB, 1);
    lsAB += __shfl_xor_sync(0xffffffffu, lsAB, 2);
    const float invA = 1.0f / lsAA;
    const float invB = 1.0f / lsAB;

    const int rowA = l0 + 8 * depA + g;    // var-A row
    const int rowB = rowA + 64;            // var-B row
    #pragma unroll
    for (int db = 0; db < 8; db++) {
        float2 v0;
        v0.x = oA[db][0] * invA;
        v0.y = oA[db][1] * invA;
        *(float2*)(out + (((size_t)(b * LL + rowA)) * HH + h) * EE + db * 8 + 2 * t) = v0;
        float2 v1;
        v1.x = oA[db][2] * invB;
        v1.y = oA[db][3] * invB;
        *(float2*)(out + (((size_t)(b * LL + rowB)) * HH + h) * EE + db * 8 + 2 * t) = v1;
    }
}

// ---------------------------------------------------------------------------
extern "C" void kernel_launch(void* const* d_in, const int* in_sizes, int n_in,
                              void* d_out, int out_size) {
    const float* q  = (const float*)d_in[0];
    const float* k  = (const float*)d_in[1];
    const float* v  = (const float*)d_in[2];
    const float* bw = (const float*)d_in[3];
    float* out = (float*)d_out;

    const int N4 = BB * LL * HH * 16;
    rope_kernel<<<(N4 + 255) / 256, 256>>>(q, k);
    pack_kernel<<<dim3(NKT, HH, BB), 256>>>(v);

    dim3 grid(LL / 128, HH, BB);
    attn7<<<grid, 256>>>(bw, out);
}

// round 10
// speedup vs baseline: 1.8270x; 1.8270x over previous
#include <cuda_runtime.h>
#include <cstdint>

#define BB 2
#define LL 2048
#define HH 16
#define EE 64
#define NKT 32

// Frag-major packed operands (tf32 bits). One warp LDG.128 = 32 consecutive uint4.
//  g_Qf/g_Kf: [bh][rowgrp(256)][kbp(4)][lane(32)]
//  g_Vf:      [bh][kt(32)][nbp(4)][db(8)][lane(32)]
__device__ uint4 g_Qf[BB * HH * 256 * 4 * 32];
__device__ uint4 g_Kf[BB * HH * 256 * 4 * 32];
__device__ uint4 g_Vf[BB * HH * NKT * 4 * 8 * 32];

#define LOG2E 1.4426950408889634f
#define SCL2  0.18033688011112042592f   // 0.125 * log2(e)

__device__ __forceinline__ uint32_t f2tf(float x) {
    uint32_t u;
    asm("cvt.rna.tf32.f32 %0, %1;" : "=r"(u) : "f"(x));
    return u;
}
__device__ __forceinline__ float ex2f(float x) {
    float o;
    asm("ex2.approx.f32 %0, %1;" : "=f"(o) : "f"(x));
    return o;
}
__device__ __forceinline__ void mma8(float c[4], const uint32_t a[4],
                                     uint32_t b0, uint32_t b1) {
    asm volatile(
        "mma.sync.aligned.m16n8k8.row.col.f32.tf32.tf32.f32 "
        "{%0,%1,%2,%3}, {%4,%5,%6,%7}, {%8,%9}, {%0,%1,%2,%3};"
        : "+f"(c[0]), "+f"(c[1]), "+f"(c[2]), "+f"(c[3])
        : "r"(a[0]), "r"(a[1]), "r"(a[2]), "r"(a[3]), "r"(b0), "r"(b1));
}

// ---------------------------------------------------------------------------
// Fused prepass: per (kt, h, b) 64-row tile — RoPE Q/K inline (element-wise,
// no inter-tile dependency), then frag-major pack of Q, K, V.
// ---------------------------------------------------------------------------
__global__ void prep_kernel(const float* __restrict__ q,
                            const float* __restrict__ k,
                            const float* __restrict__ v) {
    __shared__ float sq[64 * 65];
    __shared__ float sk[64 * 65];
    const int kt = blockIdx.x, h = blockIdx.y, b = blockIdx.z;
    const int bh = b * HH + h;
    const int tid = threadIdx.x;

    // ---- load Q,K rows (global layout [b][l][h][e]), RoPE, into smem ----
    #pragma unroll
    for (int it = 0; it < 4; it++) {
        int i = it * 256 + tid;
        int j = i >> 4, e4 = i & 15;
        int l = kt * 64 + j;
        size_t gidx = ((size_t)(b * LL + l) * HH + h) * 16 + e4;   // float4 idx
        float4 vq = ((const float4*)q)[gidx];
        float4 vk = ((const float4*)k)[gidx];
        if (e4 < 8) {
            float i0 = (float)(e4 * 2);
            const float NEG_L2 = -0.83048202372184058696f;  // -log2(10000)/16
            float s0, c0, s1, c1;
            sincosf((float)l * exp2f(i0 * NEG_L2), &s0, &c0);
            sincosf((float)l * exp2f((i0 + 1.0f) * NEG_L2), &s1, &c1);
            float4 o;
            o.x = c0 * vq.x - s0 * vq.y;  o.y = c0 * vq.y + s0 * vq.x;
            o.z = c1 * vq.z - s1 * vq.w;  o.w = c1 * vq.w + s1 * vq.z;
            vq = o;
            o.x = c0 * vk.x - s0 * vk.y;  o.y = c0 * vk.y + s0 * vk.x;
            o.z = c1 * vk.z - s1 * vk.w;  o.w = c1 * vk.w + s1 * vk.z;
            vk = o;
        }
        int e = e4 * 4;
        sq[j * 65 + e + 0] = vq.x; sq[j * 65 + e + 1] = vq.y;
        sq[j * 65 + e + 2] = vq.z; sq[j * 65 + e + 3] = vq.w;
        sk[j * 65 + e + 0] = vk.x; sk[j * 65 + e + 1] = vk.y;
        sk[j * 65 + e + 2] = vk.z; sk[j * 65 + e + 3] = vk.w;
    }
    __syncthreads();

    // ---- pack Q/K: 1024 uint4 each (8 nb x 4 kbp x 32 lanes) ----
    uint4* Qf = g_Qf + ((size_t)bh * 256 + kt * 8) * 128;
    uint4* Kf = g_Kf + ((size_t)bh * 256 + kt * 8) * 128;
    #pragma unroll
    for (int it = 0; it < 4; it++) {
        int i = it * 256 + tid;
        int lane = i & 31, x = i >> 5;       // x = nb*4 + kbp
        int nb = x >> 2, kbp = x & 3;
        int g = lane >> 2, t = lane & 3;
        const float* qs = sq + (nb * 8 + g) * 65 + kbp * 16 + t;
        uint4 o;
        o.x = f2tf(qs[0]); o.y = f2tf(qs[4]); o.z = f2tf(qs[8]); o.w = f2tf(qs[12]);
        Qf[x * 32 + lane] = o;
        const float* ks = sk + (nb * 8 + g) * 65 + kbp * 16 + t;
        o.x = f2tf(ks[0]); o.y = f2tf(ks[4]); o.z = f2tf(ks[8]); o.w = f2tf(ks[12]);
        Kf[x * 32 + lane] = o;
    }
    __syncthreads();

    // ---- load V tile into sq (reuse), then pack ----
    const float* Vg = v + ((size_t)(b * LL + kt * 64) * HH + h) * EE;
    #pragma unroll
    for (int it = 0; it < 4; it++) {
        int i = it * 256 + tid;
        int j = i >> 4, e = (i & 15) * 4;
        float4 w = *(const float4*)(Vg + (size_t)j * (HH * EE) + e);
        sq[j * 65 + e + 0] = w.x; sq[j * 65 + e + 1] = w.y;
        sq[j * 65 + e + 2] = w.z; sq[j * 65 + e + 3] = w.w;
    }
    __syncthreads();

    // V pack: 1024 uint4 (4 nbp x 8 db x 32 lanes); comp c = V[16nbp+t+4c][db*8+g]
    uint4* Vf = g_Vf + ((size_t)bh * NKT + kt) * 1024;
    #pragma unroll
    for (int it = 0; it < 4; it++) {
        int i = it * 256 + tid;
        int lane = i & 31, x = i >> 5;       // x = nbp*8 + db
        int nbp = x >> 3, db = x & 7;
        int g = lane >> 2, t = lane & 3;
        const float* vb = sq + (16 * nbp + t) * 65 + db * 8 + g;
        uint4 o;
        o.x = f2tf(vb[0]);
        o.y = f2tf(vb[4 * 65]);
        o.z = f2tf(vb[8 * 65]);
        o.w = f2tf(vb[12 * 65]);
        Vf[x * 32 + lane] = o;
    }
}

// ---------------------------------------------------------------------------
// Main attention (proven R6/R8 structure).
// 256 threads = 8 warps; CTA = 128 query rows (vars A: 0-63, B: 64-127).
// Warp w owns the depth-w paired tile (var-A group w + var-B group w);
// mask threshold 8w+g -> exactly w+1 key blocks (exact triangle).
// All hot-loop LDG.128s are fully coalesced (32 consecutive uint4).
// ---------------------------------------------------------------------------
__global__ __launch_bounds__(256, 2)
void attn6(const float* __restrict__ bw, float* __restrict__ out) {
    const int tid  = threadIdx.x;
    const int lane = tid & 31;
    const int w    = tid >> 5;       // warp = tile depth 0..7
    const int g    = lane >> 2;
    const int t    = lane & 3;
    const int qtb  = blockIdx.x;
    const int h    = blockIdx.y;
    const int b    = blockIdx.z;
    const int bh   = b * HH + h;
    const int l0   = qtb * 128;

    const float b2s = bw[HH + h] * LOG2E;
    const float b2d = bw[h] * LOG2E;

    const int rA = 8 * w + g;        // var-A local row; var-B row = rA + 64
    const int n0 = rA;               // mask threshold (both halves)

    // ---- persistent Q A-frags (coalesced frag loads) ----
    const uint4* Qfb = g_Qf + ((size_t)bh * 256 + qtb * 16 + w) * 128 + lane;
    uint32_t qa[8][4];
    #pragma unroll
    for (int kbp = 0; kbp < 4; kbp++) {
        uint4 x = Qfb[kbp * 32];               // var-A rowgrp (qtb*16 + w)
        uint4 y = Qfb[8 * 128 + kbp * 32];     // var-B rowgrp (+8)
        qa[2 * kbp][0] = x.x;      qa[2 * kbp][2] = x.y;
        qa[2 * kbp + 1][0] = x.z;  qa[2 * kbp + 1][2] = x.w;
        qa[2 * kbp][1] = y.x;      qa[2 * kbp][3] = y.y;
        qa[2 * kbp + 1][1] = y.z;  qa[2 * kbp + 1][3] = y.w;
    }

    float oacc[8][4];
    #pragma unroll
    for (int db = 0; db < 8; db++)
        #pragma unroll
        for (int i = 0; i < 4; i++) oacc[db][i] = 0.0f;
    float lsA = 0.0f, lsB = 0.0f;

    const int  src0 = (lane & ~3) + (t >> 1);
    const int  src1 = src0 + 2;
    const bool odd  = (t & 1);

    const uint4* Kf0 = g_Kf + (size_t)bh * 256 * 128 + lane;
    const uint4* Vf0 = g_Vf + (size_t)bh * NKT * 1024 + lane;

    for (int kt = 0; kt < NKT; kt++) {
        const uint4* Kt = Kf0 + (size_t)kt * 8 * 128;
        const uint4* Vt = Vf0 + (size_t)kt * 1024;
        const float biasA = (kt == 2 * qtb)     ? b2s : b2d;
        const float biasB = (kt == 2 * qtb + 1) ? b2s : b2d;

        #pragma unroll
        for (int nbp = 0; nbp < 4; nbp++) {
            const int nb0 = 2 * nbp, nb1 = nb0 + 1;
            if (nb0 > w) continue;              // warp-uniform prune
            const bool a1 = (nb1 <= w);

            // ---- K frags (fully coalesced LDG.128) ----
            uint4 kq0[4], kq1[4];
            #pragma unroll
            for (int kbp = 0; kbp < 4; kbp++)
                kq0[kbp] = Kt[nb0 * 128 + kbp * 32];
            if (a1) {
                #pragma unroll
                for (int kbp = 0; kbp < 4; kbp++)
                    kq1[kbp] = Kt[nb1 * 128 + kbp * 32];
            }

            // ---- S = Q K^T (two independent 8-mma chains) ----
            float c0[4] = {0, 0, 0, 0}, c1[4] = {0, 0, 0, 0};
            #pragma unroll
            for (int kbp = 0; kbp < 4; kbp++) {
                mma8(c0, qa[2 * kbp],     kq0[kbp].x, kq0[kbp].y);
                if (a1) mma8(c1, qa[2 * kbp],     kq1[kbp].x, kq1[kbp].y);
                mma8(c0, qa[2 * kbp + 1], kq0[kbp].z, kq0[kbp].w);
                if (a1) mma8(c1, qa[2 * kbp + 1], kq1[kbp].z, kq1[kbp].w);
            }

            // ---- softmax + P frag relayout (quad shuffles) ----
            uint32_t pa0[4], pa1[4];
            #pragma unroll
            for (int nbi = 0; nbi < 2; nbi++) {
                if (nbi && !a1) continue;
                float* c = nbi ? c1 : c0;
                const int ci = (nb0 + nbi) * 8 + 2 * t;
                float p0 = (ci     <= n0) ? ex2f(fmaf(c[0], SCL2, biasA)) : 0.0f;
                float p1 = (ci + 1 <= n0) ? ex2f(fmaf(c[1], SCL2, biasA)) : 0.0f;
                float p2 = (ci     <= n0) ? ex2f(fmaf(c[2], SCL2, biasB)) : 0.0f;
                float p3 = (ci + 1 <= n0) ? ex2f(fmaf(c[3], SCL2, biasB)) : 0.0f;
                lsA += p0 + p1;
                lsB += p2 + p3;
                uint32_t* pa = nbi ? pa1 : pa0;
                uint32_t u0 = f2tf(p0), u1 = f2tf(p1), u2 = f2tf(p2), u3 = f2tf(p3);
                uint32_t x0 = __shfl_sync(0xffffffffu, u0, src0);
                uint32_t x1 = __shfl_sync(0xffffffffu, u1, src0);
                pa[0] = odd ? x1 : x0;
                uint32_t y0 = __shfl_sync(0xffffffffu, u2, src0);
                uint32_t y1 = __shfl_sync(0xffffffffu, u3, src0);
                pa[1] = odd ? y1 : y0;
                uint32_t z0 = __shfl_sync(0xffffffffu, u0, src1);
                uint32_t z1 = __shfl_sync(0xffffffffu, u1, src1);
                pa[2] = odd ? z1 : z0;
                uint32_t w0 = __shfl_sync(0xffffffffu, u2, src1);
                uint32_t w1 = __shfl_sync(0xffffffffu, u3, src1);
                pa[3] = odd ? w1 : w0;
            }

            // ---- O += P V (coalesced V frag loads; x,y = nb0, z,w = nb1) ----
            #pragma unroll
            for (int db = 0; db < 8; db++) {
                uint4 vq = Vt[nbp * 256 + db * 32];
                mma8(oacc[db], pa0, vq.x, vq.y);
                if (a1) mma8(oacc[db], pa1, vq.z, vq.w);
            }
        }
    }

    // ---- reduce row sums across quad, normalize, store ----
    lsA += __shfl_xor_sync(0xffffffffu, lsA, 1);
    lsA += __shfl_xor_sync(0xffffffffu, lsA, 2);
    lsB += __shfl_xor_sync(0xffffffffu, lsB, 1);
    lsB += __shfl_xor_sync(0xffffffffu, lsB, 2);
    const float invA = 1.0f / lsA;
    const float invB = 1.0f / lsB;

    const int rowA = l0 + rA;
    const int rowB = rowA + 64;
    #pragma unroll
    for (int db = 0; db < 8; db++) {
        float2 v0;
        v0.x = oacc[db][0] * invA;
        v0.y = oacc[db][1] * invA;
        *(float2*)(out + (((size_t)(b * LL + rowA)) * HH + h) * EE + db * 8 + 2 * t) = v0;
        float2 v1;
        v1.x = oacc[db][2] * invB;
        v1.y = oacc[db][3] * invB;
        *(float2*)(out + (((size_t)(b * LL + rowB)) * HH + h) * EE + db * 8 + 2 * t) = v1;
    }
}

// ---------------------------------------------------------------------------
extern "C" void kernel_launch(void* const* d_in, const int* in_sizes, int n_in,
                              void* d_out, int out_size) {
    const float* q  = (const float*)d_in[0];
    const float* k  = (const float*)d_in[1];
    const float* v  = (const float*)d_in[2];
    const float* bw = (const float*)d_in[3];
    float* out = (float*)d_out;

    prep_kernel<<<dim3(NKT, HH, BB), 256>>>(q, k, v);

    dim3 grid(LL / 128, HH, BB);
    attn6<<<grid, 256>>>(bw, out);
}